// round 5
// baseline (speedup 1.0000x reference)
#include <cuda_runtime.h>

#define NS  16384        // sources
#define NT  16384        // targets
#define NB  32           // batch
#define NBR 64           // branches per source
#define NE  (NS * NBR)   // 1,048,576 entries
#define CAP 192          // per-target record capacity (avg 64, max ~115)

// Scratch (no cudaMalloc allowed)
__device__ float  g_spikesT[NS * NB];   // spikes transposed [S, B]  (2 MB)
__device__ int    g_cursor[NT];         // per-target entry count (zero-init; gather re-zeroes)
__device__ float2 g_recs[NT * CAP];     // (weight, source-as-bits) (25 MB, L2-resident)

__constant__ float c_decay[8] = {
    1.0f, 0.9f, 0.81f, 0.729f, 0.6561f, 0.59049f, 0.531441f, 0.4782969f
};

// ---------------------------------------------------------------------------
// Kernel 1 (fused): blocks [0, NBIN) bin entries by target;
// blocks [NBIN, NBIN+512) transpose spikes [B,S] -> [S,B].
// No ordering hazard: nothing here reads what the other half writes.
// Cursors are pre-zeroed (static init on call 1, k_gather resets thereafter).
#define BIN_BLK 256
#define NBIN (NE / (BIN_BLK * 4))   // 1024 bin blocks, 4 entries/thread

__global__ void __launch_bounds__(256) k_bin(const float* __restrict__ spikes,
                                             const float* __restrict__ att,
                                             const int*   __restrict__ tgt,
                                             const int*   __restrict__ del) {
    if (blockIdx.x < NBIN) {
        // ---- binning: 4 entries per thread via 128-bit loads ----
        const int base = (blockIdx.x * BIN_BLK + threadIdx.x) * 4;  // entry index
        const float4 a4 = *reinterpret_cast<const float4*>(att + base);
        const int4   t4 = *reinterpret_cast<const int4*>(tgt + base);
        const int4   d4 = *reinterpret_cast<const int4*>(del + base);

        const float w0 = fminf(fmaxf(a4.x, 0.f), 1.f) * c_decay[d4.x & 7];
        const float w1 = fminf(fmaxf(a4.y, 0.f), 1.f) * c_decay[d4.y & 7];
        const float w2 = fminf(fmaxf(a4.z, 0.f), 1.f) * c_decay[d4.z & 7];
        const float w3 = fminf(fmaxf(a4.w, 0.f), 1.f) * c_decay[d4.w & 7];

        const int p0 = atomicAdd(&g_cursor[t4.x], 1);
        const int p1 = atomicAdd(&g_cursor[t4.y], 1);
        const int p2 = atomicAdd(&g_cursor[t4.z], 1);
        const int p3 = atomicAdd(&g_cursor[t4.w], 1);

        const int s0 = (base + 0) >> 6, s1 = (base + 1) >> 6;
        const int s2 = (base + 2) >> 6, s3 = (base + 3) >> 6;

        if (p0 < CAP) g_recs[t4.x * CAP + p0] = make_float2(w0, __int_as_float(s0));
        if (p1 < CAP) g_recs[t4.y * CAP + p1] = make_float2(w1, __int_as_float(s1));
        if (p2 < CAP) g_recs[t4.z * CAP + p2] = make_float2(w2, __int_as_float(s2));
        if (p3 < CAP) g_recs[t4.w * CAP + p3] = make_float2(w3, __int_as_float(s3));
    } else {
        // ---- spike transpose: one 32x32 tile per block, 256 threads ----
        __shared__ float tile[32][33];
        const int blk = blockIdx.x - NBIN;       // 0..511
        const int s0 = blk * 32;
        const int tx = threadIdx.x & 31;
        const int ty = threadIdx.x >> 5;         // 0..7
#pragma unroll
        for (int k = 0; k < 4; k++) {
            const int b = ty + 8 * k;
            tile[b][tx] = spikes[b * NS + s0 + tx];     // coalesced along s
        }
        __syncthreads();
#pragma unroll
        for (int k = 0; k < 4; k++) {
            const int r = ty + 8 * k;
            g_spikesT[(s0 + r) * NB + tx] = tile[tx][r]; // coalesced along b
        }
    }
}

// ---------------------------------------------------------------------------
// Kernel 2: gather. One warp per target. Warp is split into 4 entry-groups
// (g = lane>>3) x 8 lanes (l = lane&7); each lane loads a float4 of the spike
// row (batches 4l..4l+3), so one warp-iteration consumes 4 entries with
// 1 LDG.64 + 1 LDG.128 + 16 FFMA. Cross-group shfl reduction, smem transpose,
// coalesced store. Also resets g_cursor for the next graph replay.
__global__ void __launch_bounds__(1024, 2) k_gather(float* __restrict__ out) {
    __shared__ float tile[32][33];
    const int lane = threadIdx.x & 31;
    const int wrp  = threadIdx.x >> 5;     // target within CTA
    const int t0   = blockIdx.x * 32;
    const int t    = t0 + wrp;
    const int g    = lane >> 3;            // entry subgroup 0..3
    const int l    = lane & 7;             // batch-quad index 0..7

    int n = min(g_cursor[t], CAP);
    if (lane == 0) g_cursor[t] = 0;        // leave zeroed for next launch
    const float2* __restrict__ rec = g_recs + t * CAP;

    float4 acc = make_float4(0.f, 0.f, 0.f, 0.f);
#pragma unroll 2
    for (int j = 0; j < n; j += 4) {
        const int  e  = min(j + g, n - 1);
        const float2 r = rec[e];
        const float  w = (j + g < n) ? r.x : 0.f;
        const float4 v = reinterpret_cast<const float4*>(
                             g_spikesT + __float_as_int(r.y) * NB)[l];
        acc.x = fmaf(w, v.x, acc.x);
        acc.y = fmaf(w, v.y, acc.y);
        acc.z = fmaf(w, v.z, acc.z);
        acc.w = fmaf(w, v.w, acc.w);
    }

    // reduce the 4 entry-groups (lanes differing in bits 3,4)
#pragma unroll
    for (int off = 8; off <= 16; off <<= 1) {
        acc.x += __shfl_xor_sync(0xFFFFFFFFu, acc.x, off);
        acc.y += __shfl_xor_sync(0xFFFFFFFFu, acc.y, off);
        acc.z += __shfl_xor_sync(0xFFFFFFFFu, acc.z, off);
        acc.w += __shfl_xor_sync(0xFFFFFFFFu, acc.w, off);
    }

    if (g == 0) {                          // lanes 0..7 hold batches 4l..4l+3
        tile[4 * l + 0][wrp] = acc.x;
        tile[4 * l + 1][wrp] = acc.y;
        tile[4 * l + 2][wrp] = acc.z;
        tile[4 * l + 3][wrp] = acc.w;
    }
    __syncthreads();
    // warp wrp writes batch row b = wrp: out[b][t0 + lane], coalesced
    out[wrp * NT + t0 + lane] = tile[wrp][lane];
}

// ---------------------------------------------------------------------------
extern "C" void kernel_launch(void* const* d_in, const int* in_sizes, int n_in,
                              void* d_out, int out_size) {
    const float* spikes = (const float*)d_in[0];   // [B, S] f32
    const float* att    = (const float*)d_in[1];   // [S, Br] f32
    const int*   tgt    = (const int*)  d_in[2];   // [S, Br] i32
    const int*   del    = (const int*)  d_in[3];   // [S, Br] i32
    float* out = (float*)d_out;                    // [B, T] f32

    k_bin<<<NBIN + NS / 32, BIN_BLK>>>(spikes, att, tgt, del);
    k_gather<<<NT / 32, 1024>>>(out);
}